// round 4
// baseline (speedup 1.0000x reference)
#include <cuda_runtime.h>

#define Tlen 1000
#define Bsz  4096
#define INsz 8
#define Hsz  50
#define Osz  6
#define NDIM 56
// j index space (64): j<50 -> W_rec/W_out vs relu(h); 50..55 -> zero pad;
//                     56..63 -> W_in vs x_t
// word map within a row: wd(j) = j<32 ? j : j+4   (h0: words 0..31, h1: 36..67)
#define VROW 68   // v row stride (17 chunks)
#define WROW 76   // w row stride (19 chunks; (dg,h) bank-groups {0,1,5,6})
#define BTILE 32

__device__ __forceinline__ void fma2(unsigned long long& acc,
                                     unsigned long long a,
                                     unsigned long long b) {
    asm("fma.rn.f32x2 %0, %1, %2, %0;" : "+l"(acc) : "l"(a), "l"(b));
}

__device__ __forceinline__ float hadd2(unsigned long long a) {
    float lo, hi;
    asm("mov.b64 {%0, %1}, %2;" : "=f"(lo), "=f"(hi) : "l"(a));
    return lo + hi;
}

__global__ void __launch_bounds__(256, 1) biornn_kernel(
    const float* __restrict__ x,       // (T, B, 8)
    const float* __restrict__ W_in,    // (50, 8)
    const float* __restrict__ W_rec,   // (50, 50)
    const float* __restrict__ bias,    // (50,)
    const float* __restrict__ W_out_w, // (6, 50)
    const float* __restrict__ W_out_b, // (6,)
    float* __restrict__ out)           // (T, B, 6)
{
    __shared__ __align__(16) float sW[NDIM * WROW];
    __shared__ __align__(16) float sV[2 * BTILE * VROW];
    __shared__ float sB[NDIM];

    const int tid = threadIdx.x;

    // ---- stage weights ----
    for (int i = tid; i < NDIM * WROW; i += 256) {
        int d = i / WROW, w = i - d * WROW;
        int j = (w < 32) ? w : ((w >= 36 && w < 68) ? (w - 4) : -1);
        float val = 0.f;
        if (j >= 0) {
            if (d < Hsz) {
                if (j < Hsz)       val = W_rec[d * Hsz + j];
                else if (j >= 56)  val = W_in[d * INsz + (j - 56)];
            } else {
                if (j < Hsz)       val = W_out_w[(d - Hsz) * Hsz + j];
            }
        }
        sW[i] = val;
    }
    for (int i = tid; i < 2 * BTILE * VROW; i += 256) sV[i] = 0.f;
    for (int i = tid; i < NDIM; i += 256)
        sB[i] = (i < Hsz) ? bias[i] : W_out_b[i - Hsz];
    __syncthreads();

    const int lane = tid & 31;
    const int wrp  = tid >> 5;
    const int wq   = wrp & 3;            // dim quarter (14 dims)
    const int wb   = wrp >> 2;           // batch half (16 batches)
    const int b    = lane & 7;
    const int dg   = (lane >> 3) & 1;    // dim sub-group (7 dims)
    const int h    = lane >> 4;          // j half

    const int dbase  = wq * 14 + dg * 7;
    const int bb0    = wb * 16 + b;      // thread's two batches: bb0, bb0+8
    const int pubbat = bb0 + 8 * h;      // batch this lane publishes/owns
    const int gb0    = blockIdx.x * BTILE;
    const bool is_y  = (wq == 3 && dg == 1);   // dims 49..55 (dl0 = 49 is h-dim)

    float hreg[7], br[7];
    int wd[7];
    #pragma unroll
    for (int dl = 0; dl < 7; dl++) {
        int d = dbase + dl;
        hreg[dl] = 0.f;
        br[dl]   = sB[d];
        wd[dl]   = (d < 32) ? d : d + 4;
    }

    const float* wbase = sW + dbase * WROW + h * 36;

    // ---- x prefetch: warps wq==0 cover all 32 batches; dg splits the 8 floats ----
    float4 xreg;
    const float4* xp = reinterpret_cast<const float4*>(x);
    if (wq == 0)
        xreg = xp[((size_t)0 * Bsz + gb0 + pubbat) * 2 + dg];

    #pragma unroll 1
    for (int t = 0; t < Tlen; t++) {
        float* vb  = sV + (t & 1) * (BTILE * VROW);
        float* own = vb + pubbat * VROW;

        // ---- publish r = relu(h) ----
        if (!is_y) {
            #pragma unroll
            for (int dl = 0; dl < 7; dl++)
                own[wd[dl]] = fmaxf(hreg[dl], 0.f);
        } else {
            own[wd[0]] = fmaxf(hreg[0], 0.f);   // d = 49
        }

        // ---- publish x_t, prefetch x_{t+1} ----
        if (wq == 0) {
            *reinterpret_cast<float4*>(own + 60 + dg * 4) = xreg;
            if (t + 1 < Tlen)
                xreg = xp[((size_t)(t + 1) * Bsz + gb0 + pubbat) * 2 + dg];
        }
        __syncthreads();

        // ---- half-matvec: 7 dims x 2 batches x 32 j (this lane's half) ----
        unsigned long long acc0[7], acc1[7];
        #pragma unroll
        for (int dl = 0; dl < 7; dl++) { acc0[dl] = 0ull; acc1[dl] = 0ull; }

        const ulonglong2* va =
            reinterpret_cast<const ulonglong2*>(vb + bb0 * VROW + h * 36);
        const ulonglong2* vc =
            reinterpret_cast<const ulonglong2*>(vb + (bb0 + 8) * VROW + h * 36);

        #pragma unroll
        for (int jb = 0; jb < 8; jb++) {
            ulonglong2 a = va[jb];
            ulonglong2 c = vc[jb];
            #pragma unroll
            for (int dl = 0; dl < 7; dl++) {
                ulonglong2 w =
                    reinterpret_cast<const ulonglong2*>(wbase + dl * WROW)[jb];
                fma2(acc0[dl], a.x, w.x);
                fma2(acc0[dl], a.y, w.y);
                fma2(acc1[dl], c.x, w.x);
                fma2(acc1[dl], c.y, w.y);
            }
        }

        // ---- combine j-halves across h lanes; finalize own batch ----
        size_t obase = ((size_t)t * Bsz + gb0 + pubbat) * Osz;
        #pragma unroll
        for (int dl = 0; dl < 7; dl++) {
            float s0 = hadd2(acc0[dl]);
            float s1 = hadd2(acc1[dl]);
            s0 += __shfl_xor_sync(0xffffffffu, s0, 16);
            s1 += __shfl_xor_sync(0xffffffffu, s1, 16);
            float so = (h ? s1 : s0) + br[dl];
            if (!is_y || dl == 0) {
                hreg[dl] = fmaf(0.1f, so - hreg[dl], hreg[dl]);
            } else {
                out[obase + (dl - 1)] = so;
            }
        }
    }
}

extern "C" void kernel_launch(void* const* d_in, const int* in_sizes, int n_in,
                              void* d_out, int out_size) {
    const float* x        = (const float*)d_in[0];
    const float* W_in     = (const float*)d_in[1];
    const float* W_rec    = (const float*)d_in[2];
    const float* bias     = (const float*)d_in[3];
    const float* W_out_w  = (const float*)d_in[4];
    const float* W_out_b  = (const float*)d_in[5];
    float* out = (float*)d_out;

    biornn_kernel<<<Bsz / BTILE, 256>>>(x, W_in, W_rec, bias,
                                        W_out_w, W_out_b, out);
}